// round 10
// baseline (speedup 1.0000x reference)
#include <cuda_runtime.h>
#include <cstdint>

#define N_STFT   1025
#define N_MELS   128
#define BATCH    4
#define TIME     1024
#define ROWS     (BATCH*TIME)
#define MAX_ITER 20
#define LR       0.3f
#define MOM      0.9f
#define INVC     (2.0f/4096.0f)
#define CH       33            // bins per lane
#define CHA      17            // chain A bins 0..16
#define CHB      16            // chain B bins 17..32
#define WPB      4             // warps (rows) per CTA
#define THREADS  (WPB*32)
#define FPAD     (32*CH)       // 1056
#define NENT     132           // entries: virtual mels -1..130
#define ENTB     36u           // entry pitch bytes (9 words, gcd(9,32)=1)

// ---------------- device globals ----------------
__device__ float         g_aw[FPAD];
__device__ unsigned char g_me[FPAD];

// ---------------- table build: one warp per frequency ----------------
__global__ void build_tables_k(const float* __restrict__ fb) {
    int gw   = (blockIdx.x * blockDim.x + threadIdx.x) >> 5;
    int lane = threadIdx.x & 31;
    if (gw >= FPAD) return;
    if (gw >= N_STFT) {
        if (!lane) { g_aw[gw] = 1.0f; g_me[gw] = 129; }
        return;
    }
    const float* r = fb + (size_t)gw * N_MELS;
    int m4 = lane * 4;
    unsigned loc = 128u;
    #pragma unroll
    for (int k = 3; k >= 0; k--) if (r[m4 + k] != 0.f) loc = (unsigned)(m4 + k);
    #pragma unroll
    for (int o = 16; o; o >>= 1) {
        unsigned v = __shfl_xor_sync(0xffffffffu, loc, o);
        loc = v < loc ? v : loc;
    }
    if (!lane) {
        float aw; int me;
        if (loc >= 128u) {                    // all-zero row: f=0 or f=1024
            aw = 1.0f; me = (gw == 0) ? 0 : 129;
        } else {
            int m0 = (int)loc;
            float w0raw = r[m0];
            float w1raw = (m0 < N_MELS - 1) ? r[m0 + 1] : 0.f;
            if (m0 == 0 && w1raw == 0.f && w0raw < 1.0f) {
                me = 0;                        // ascending-only: virtual mel -1
                aw = fmaxf(1.0f - w0raw, 1e-6f);
            } else {
                me = m0 + 1; aw = w0raw;       // w1 = 1 - aw (overlap identity)
            }
        }
        g_aw[gw] = aw; g_me[gw] = (unsigned char)me;
    }
}

// ---------------- asm helpers ----------------
__device__ __forceinline__ unsigned smaddr(const void* p) {
    return (unsigned)__cvta_generic_to_shared(p);
}
__device__ __forceinline__ void sts_f32(unsigned a, float v) {
    asm volatile("st.shared.f32 [%0], %1;" :: "r"(a), "f"(v) : "memory");
}
__device__ __forceinline__ float lds_f32(unsigned a) {
    float v; asm volatile("ld.shared.f32 %0, [%1];" : "=f"(v) : "r"(a)); return v;
}
// Entry layout (36 B): {ex, ey, acc0, acc1, acc2, acc3, acc4, pad, pad}
// On mel change (sign(w0)<0): flush a0 -> acc0 of completed entry, shift
// a0<-a1, a1<-0, load new entry's (ex,ey) into (d0,d1), advance cursor.
#define CTRL(w0i, ad, a0, a1, d0, d1) asm volatile(      \
    "{\n\t.reg .pred p;\n\t"                             \
    "setp.lt.f32 p, %5, 0f00000000;\n\t"                 \
    "@p st.shared.f32 [%0+8], %1;\n\t"                   \
    "selp.f32 %1, %2, %1, p;\n\t"                        \
    "selp.f32 %2, 0f00000000, %2, p;\n\t"                \
    "@p ld.shared.f32 %3, [%0+36];\n\t"                  \
    "@p ld.shared.f32 %4, [%0+40];\n\t"                  \
    "@p add.u32 %0, %0, 36;\n\t}"                        \
    : "+r"(ad), "+f"(a0), "+f"(a1), "+f"(d0), "+f"(d1)   \
    : "f"(w0i) : "memory")
// forward-only variant (prologue)
#define CTRLF(w0i, ad, a0, a1) asm volatile(             \
    "{\n\t.reg .pred p;\n\t"                             \
    "setp.lt.f32 p, %3, 0f00000000;\n\t"                 \
    "@p st.shared.f32 [%0+8], %1;\n\t"                   \
    "selp.f32 %1, %2, %1, p;\n\t"                        \
    "selp.f32 %2, 0f00000000, %2, p;\n\t"                \
    "@p add.u32 %0, %0, 36;\n\t}"                        \
    : "+r"(ad), "+f"(a0), "+f"(a1)                       \
    : "f"(w0i) : "memory")

#define BODY(i, d0, d1, a0, a1) do {                     \
    float aw_ = fabsf(w0[i]);                            \
    float g_  = fmaf(aw_, (d0) - (d1), (d1));            \
    bu[i] = fmaf(MOM, bu[i], g_);                        \
    sp[i] = fmaxf(fmaf(-LR, bu[i], sp[i]), 0.f);         \
    (a0) = fmaf(sp[i], aw_, (a0));                       \
    (a1) = fmaf(sp[i], 1.0f - aw_, (a1));                \
} while (0)

#define BODYF(i, a0, a1) do {                            \
    float aw_ = fabsf(w0[i]);                            \
    (a0) = fmaf(sp[i], aw_, (a0));                       \
    (a1) = fmaf(sp[i], 1.0f - aw_, (a1));                \
} while (0)

// ---------------- shared: iteration phase / epilogue stage union ----------------
struct __align__(16) SmemIter {
    float ent[WPB][NENT][9];   // 36 B per entry, zero-initialized once
};
union __align__(16) SmemU {
    SmemIter it;
    float    stage[WPB][FPAD];
};

// ---------------- main: warp = one (b,t) row; 20 fused iterations ----------------
__global__ void __launch_bounds__(THREADS, 4)
imel_k(const float* __restrict__ mel, const float* __restrict__ spi,
       float* __restrict__ out)
{
    __shared__ SmemU S;
    const int tid  = threadIdx.x;
    const int wid  = tid >> 5;
    const int lane = tid & 31;
    const int row  = blockIdx.x * WPB + wid;
    const int b    = row >> 10;
    const int t    = row & (TIME - 1);

    // one-time zero of all entries (write pattern static across iterations)
    {
        float4  z  = make_float4(0.f, 0.f, 0.f, 0.f);
        float4* pz = reinterpret_cast<float4*>(&S.it.ent[0][0][0]);
        #pragma unroll 1
        for (int k = tid; k < WPB*NENT*9/4; k += THREADS) pz[k] = z;
    }

    const int f_lo = lane * CH;

    // register state; sign(w0[i]) = "mel changes between bin i-1 and i"
    float w0[CH], sp[CH], bu[CH];
    int me0 = 0, meB = 0, pme = 0;
    #pragma unroll
    for (int i = 0; i < CH; i++) {
        int f  = f_lo + i;
        int fc = f > N_STFT-1 ? N_STFT-1 : f;
        float aw = g_aw[f];
        int   me = (int)g_me[f];
        sp[i] = spi[(size_t)row * N_STFT + fc];
        bu[i] = 0.f;
        if (i == 0) { me0 = me; w0[0] = aw; }
        else        { w0[i] = (me != pme) ? -aw : aw; }
        if (i == CHA) meB = me;                 // chain B start entry
        pme = me;
    }
    float melI[4];
    #pragma unroll
    for (int j = 0; j < 4; j++)
        melI[j] = mel[(size_t)b*(N_MELS*TIME) + (size_t)(lane + 32*j)*TIME + t] * INVC;

    const unsigned entb = smaddr(&S.it.ent[wid][0][0]);
    const unsigned adA0 = entb + (unsigned)me0 * ENTB;
    const unsigned adB0 = entb + (unsigned)meB * ENTB;

    __syncthreads();   // zeros visible (block-wide init)

    // ---- prologue forward: scatter proj of iteration 0 (two chains) ----
    {
        unsigned adA = adA0, adB = adB0;
        float a0A = 0.f, a1A = 0.f, a0B = 0.f, a1B = 0.f;
        #pragma unroll
        for (int k = 0; k < CHA; k++) {
            if (k > 0) CTRLF(w0[k], adA, a0A, a1A);
            BODYF(k, a0A, a1A);
            if (k < CHB) {
                if (k > 0) CTRLF(w0[CHA + k], adB, a0B, a1B);
                BODYF(CHA + k, a0B, a1B);
            }
        }
        sts_f32(adA + 12u, a0A);   // acc1 of A-end entry
        sts_f32(adA + 52u, a1A);   // acc2 of A-end entry + 1
        sts_f32(adB + 20u, a0B);   // acc3 of B-end entry
        sts_f32(adB + 60u, a1B);   // acc4 of B-end entry + 1
    }
    __syncwarp();

    #pragma unroll 1
    for (int it = 0; it < MAX_ITER; it++) {
        // ---- combine: e[m] = INVC*proj[m] - INVC*mel[m]; write (ex,ey) rep ----
        #pragma unroll
        for (int j = 0; j < 4; j++) {
            int m = lane + 32*j;
            unsigned ea = entb + (unsigned)(m + 1) * ENTB;
            float x0 = lds_f32(ea + 8u);
            float x1 = lds_f32(ea + 12u);
            float x2 = lds_f32(ea + 16u);
            float x3 = lds_f32(ea + 20u);
            float x4 = lds_f32(ea + 24u);
            float s  = ((x0 + x1) + (x2 + x3)) + x4;
            float e  = fmaf(s, INVC, -melI[j]);
            sts_f32(ea, e);          // ex of entry m+1 = e[m]
            sts_f32(ea - 32u, e);    // ey of entry m   = e[m]
        }
        __syncwarp();

        // ---- fused backward(it) + forward(it+1); two interleaved chains ----
        unsigned adA = adA0, adB = adB0;
        float d0A = lds_f32(adA0), d1A = lds_f32(adA0 + 4u);
        float d0B = lds_f32(adB0), d1B = lds_f32(adB0 + 4u);
        float a0A = 0.f, a1A = 0.f, a0B = 0.f, a1B = 0.f;
        #pragma unroll
        for (int k = 0; k < CHA; k++) {
            if (k > 0) CTRL(w0[k], adA, a0A, a1A, d0A, d1A);
            BODY(k, d0A, d1A, a0A, a1A);
            if (k < CHB) {
                if (k > 0) CTRL(w0[CHA + k], adB, a0B, a1B, d0B, d1B);
                BODY(CHA + k, d0B, d1B, a0B, a1B);
            }
        }
        sts_f32(adA + 12u, a0A);
        sts_f32(adA + 52u, a1A);
        sts_f32(adB + 20u, a0B);
        sts_f32(adB + 60u, a1B);
        __syncwarp();
    }

    // ---- epilogue: stage rows in shared, write (B,F,T) with STG.128 ----
    __syncthreads();               // all warps done with union before reuse
    {
        float* stg = &S.stage[wid][0];
        #pragma unroll
        for (int i = 0; i < CH; i++) stg[f_lo + i] = sp[i];
    }
    __syncthreads();
    {
        const int rb = blockIdx.x * WPB;
        const int t0 = rb & (TIME - 1);
        const int bb = rb >> 10;
        float4* ob = reinterpret_cast<float4*>(out + (size_t)bb * N_STFT * TIME + t0);
        #pragma unroll 1
        for (int f = tid; f < N_STFT; f += THREADS) {
            float4 v = make_float4(S.stage[0][f], S.stage[1][f],
                                   S.stage[2][f], S.stage[3][f]);
            ob[(size_t)f * (TIME/4)] = v;
        }
    }
}

// ---------------- launch ----------------
extern "C" void kernel_launch(void* const* d_in, const int* in_sizes, int n_in,
                              void* d_out, int out_size) {
    const float* mel = nullptr;   // 4*128*1024
    const float* spi = nullptr;   // 4*1024*1025
    const float* fb  = nullptr;   // 1025*128
    for (int i = 0; i < n_in; i++) {
        if      (in_sizes[i] == BATCH * N_MELS * TIME) mel = (const float*)d_in[i];
        else if (in_sizes[i] == ROWS * N_STFT)         spi = (const float*)d_in[i];
        else if (in_sizes[i] == N_STFT * N_MELS)       fb  = (const float*)d_in[i];
    }
    float* out = (float*)d_out;

    build_tables_k<<<(FPAD*32 + 255)/256, 256>>>(fb);   // warp per frequency
    imel_k<<<ROWS/WPB, THREADS>>>(mel, spi, out);
}

// round 12
// speedup vs baseline: 1.0921x; 1.0921x over previous
#include <cuda_runtime.h>
#include <cstdint>

#define N_STFT   1025
#define N_MELS   128
#define BATCH    4
#define TIME     1024
#define ROWS     (BATCH*TIME)
#define MAX_ITER 20
#define LR       0.3f
#define MOM      0.9f
#define INVC     (2.0f/4096.0f)
#define CH       33            // bins per lane (32*33 = 1056 >= 1025)
#define WPB      4             // warps (rows) per CTA
#define THREADS  (WPB*32)
#define FPAD     (32*CH)       // 1056
#define NENT     132           // entries k = virtual mel + 1, k in 0..131
#define ENTB     20u           // entry pitch bytes (5 words, gcd(5,32)=1 -> conflict-free)

// ---------------- device globals ----------------
// aw = |weight| of entry-mel; me = virtual mel + 1 (0..129); w1 = 1 - aw implied.
__device__ float         g_aw[FPAD];
__device__ unsigned char g_me[FPAD];

// ---------------- table build: one warp per frequency ----------------
__global__ void build_tables_k(const float* __restrict__ fb) {
    int gw   = (blockIdx.x * blockDim.x + threadIdx.x) >> 5;
    int lane = threadIdx.x & 31;
    if (gw >= FPAD) return;
    if (gw >= N_STFT) {
        if (!lane) { g_aw[gw] = 1.0f; g_me[gw] = 129; }
        return;
    }
    const float* r = fb + (size_t)gw * N_MELS;
    int m4 = lane * 4;
    unsigned loc = 128u;
    #pragma unroll
    for (int k = 3; k >= 0; k--) if (r[m4 + k] != 0.f) loc = (unsigned)(m4 + k);
    #pragma unroll
    for (int o = 16; o; o >>= 1) {
        unsigned v = __shfl_xor_sync(0xffffffffu, loc, o);
        loc = v < loc ? v : loc;
    }
    if (!lane) {
        float aw; int me;
        if (loc >= 128u) {                    // all-zero row: f=0 or f=1024
            aw = 1.0f; me = (gw == 0) ? 0 : 129;
        } else {
            int m0 = (int)loc;
            float w0raw = r[m0];
            float w1raw = (m0 < N_MELS - 1) ? r[m0 + 1] : 0.f;
            if (m0 == 0 && w1raw == 0.f && w0raw < 1.0f) {
                me = 0;                        // ascending-only: virtual mel -1
                aw = fmaxf(1.0f - w0raw, 1e-6f);
            } else {
                me = m0 + 1; aw = w0raw;       // w1 = 1 - aw (overlap identity)
            }
        }
        g_aw[gw] = aw; g_me[gw] = (unsigned char)me;
    }
}

// ---------------- asm helpers ----------------
__device__ __forceinline__ unsigned smaddr(const void* p) {
    return (unsigned)__cvta_generic_to_shared(p);
}
__device__ __forceinline__ void sts_f32(unsigned a, float v) {
    asm volatile("st.shared.f32 [%0], %1;" :: "r"(a), "f"(v) : "memory");
}
__device__ __forceinline__ float lds_f32(unsigned a) {
    float v; asm volatile("ld.shared.f32 %0, [%1];" : "=f"(v) : "r"(a)); return v;
}
// Entry layout (20 B): {efield, acc0, acc1, acc2, pad}.
// efield[k] = e_mel[k-1]; acc slots of entry k accumulate proj[vm = k-1]:
//   acc0 = in-loop flush (unique boundary writer), acc1 = a0 end-flush,
//   acc2 = a1 end-flush (written at end entry + 1).
// Mel steps are exactly +1, so on a change: d0 <- d1, d1 <- pn (prefetched),
// and pn reloads efield two entries ahead of the new cursor — its consumer is
// the NEXT change, hiding the 29-cyc LDS latency.
#define CTRL(w0i) asm volatile(                          \
    "{\n\t.reg .pred p;\n\t"                             \
    "setp.lt.f32 p, %5, 0f00000000;\n\t"                 \
    "@p st.shared.f32 [%0+4], %1;\n\t"                   \
    "selp.f32 %1, %2, %1, p;\n\t"                        \
    "selp.f32 %2, 0f00000000, %2, p;\n\t"                \
    "selp.f32 %3, %4, %3, p;\n\t"                        \
    "@p add.u32 %0, %0, 20;\n\t"                         \
    "selp.f32 %4, %6, %4, p;\n\t"                        \
    "@p ld.shared.f32 %6, [%0+40];\n\t}"                 \
    : "+r"(addr), "+f"(a0), "+f"(a1), "+f"(d0),          \
      "+f"(d1), "+f"(w0i), "+f"(pn)                      \
    :: "memory")
// forward-only variant (prologue)
#define CTRLF(w0i) asm volatile(                         \
    "{\n\t.reg .pred p;\n\t"                             \
    "setp.lt.f32 p, %3, 0f00000000;\n\t"                 \
    "@p st.shared.f32 [%0+4], %1;\n\t"                   \
    "selp.f32 %1, %2, %1, p;\n\t"                        \
    "selp.f32 %2, 0f00000000, %2, p;\n\t"                \
    "@p add.u32 %0, %0, 20;\n\t}"                        \
    : "+r"(addr), "+f"(a0), "+f"(a1)                     \
    : "f"(w0i) : "memory")

// ---------------- shared: iteration phase / epilogue stage union ----------------
struct __align__(16) SmemIter {
    float ent[WPB][NENT][5];   // 20 B per entry, zero-initialized once
};
union __align__(16) SmemU {
    SmemIter it;
    float    stage[WPB][FPAD];
};

// ---------------- main: warp = one (b,t) row; 20 fused iterations ----------------
__global__ void __launch_bounds__(THREADS, 4)
imel_k(const float* __restrict__ mel, const float* __restrict__ spi,
       float* __restrict__ out)
{
    __shared__ SmemU S;
    const int tid  = threadIdx.x;
    const int wid  = tid >> 5;
    const int lane = tid & 31;
    const int row  = blockIdx.x * WPB + wid;
    const int b    = row >> 10;
    const int t    = row & (TIME - 1);

    // one-time zero of all entries (write pattern static across iterations;
    // efield of virtual-mel entries 0,129..131 stays 0 forever)
    {
        float4  z  = make_float4(0.f, 0.f, 0.f, 0.f);
        float4* pz = reinterpret_cast<float4*>(&S.it.ent[0][0][0]);
        #pragma unroll 1
        for (int k = tid; k < WPB*NENT*5/4; k += THREADS) pz[k] = z;
    }

    const int f_lo = lane * CH;

    // register state; sign(w0[i]) = "mel changes between bin i-1 and i"
    float w0[CH], sp[CH], bu[CH];
    int me0 = 0, pme = 0;
    #pragma unroll
    for (int i = 0; i < CH; i++) {
        int f  = f_lo + i;
        int fc = f > N_STFT-1 ? N_STFT-1 : f;
        float aw = g_aw[f];
        int   me = (int)g_me[f];
        sp[i] = spi[(size_t)row * N_STFT + fc];
        bu[i] = 0.f;
        if (i == 0) { me0 = me; w0[0] = aw; }
        else        { w0[i] = (me != pme) ? -aw : aw; }
        pme = me;
    }
    float melI[4];
    #pragma unroll
    for (int j = 0; j < 4; j++)
        melI[j] = mel[(size_t)b*(N_MELS*TIME) + (size_t)(lane + 32*j)*TIME + t] * INVC;

    const unsigned entb = smaddr(&S.it.ent[wid][0][0]);
    const unsigned ad0  = entb + (unsigned)me0 * ENTB;

    __syncthreads();   // zeros visible (block-wide init)

    // ---- prologue forward: scatter proj of iteration 0 ----
    {
        unsigned addr = ad0;
        float a0 = 0.f, a1 = 0.f;
        #pragma unroll
        for (int i = 0; i < CH; i++) {
            if (i > 0) CTRLF(w0[i]);
            float aw = fabsf(w0[i]);
            a0 = fmaf(sp[i], aw, a0);
            a1 = fmaf(sp[i], 1.0f - aw, a1);
        }
        sts_f32(addr + 8u,  a0);   // acc1 of end entry
        sts_f32(addr + 32u, a1);   // acc2 of end entry + 1 (20 + 12)
    }
    __syncwarp();

    #pragma unroll 1
    for (int it = 0; it < MAX_ITER; it++) {
        // ---- combine: efield[m+1] = INVC*proj[m] - INVC*mel[m] ----
        #pragma unroll
        for (int j = 0; j < 4; j++) {
            int m = lane + 32*j;
            unsigned ea = entb + (unsigned)(m + 1) * ENTB;
            float x0 = lds_f32(ea + 4u);
            float x1 = lds_f32(ea + 8u);
            float x2 = lds_f32(ea + 12u);
            float e  = fmaf((x0 + x1) + x2, INVC, -melI[j]);
            sts_f32(ea, e);
        }
        __syncwarp();

        // ---- fused backward(it) + forward(it+1); d-pair shifts, pn prefetched ----
        unsigned addr = ad0;
        float d0 = lds_f32(ad0);          // efield[k]   = e_mel[vm]
        float d1 = lds_f32(ad0 + 20u);    // efield[k+1] = e_mel[vm+1]
        float pn = lds_f32(ad0 + 40u);    // efield[k+2] (next change's d1)
        float a0 = 0.f, a1 = 0.f;
        #pragma unroll
        for (int i = 0; i < CH; i++) {
            if (i > 0) CTRL(w0[i]);
            float aw = fabsf(w0[i]);
            float g  = fmaf(aw, d0 - d1, d1);     // e[vm]*aw + e[vm+1]*(1-aw)
            bu[i] = fmaf(MOM, bu[i], g);
            sp[i] = fmaxf(fmaf(-LR, bu[i], sp[i]), 0.f);
            a0 = fmaf(sp[i], aw, a0);             // forward for next iteration
            a1 = fmaf(sp[i], 1.0f - aw, a1);
        }
        sts_f32(addr + 8u,  a0);
        sts_f32(addr + 32u, a1);
        __syncwarp();
    }

    // ---- epilogue: stage rows in shared, write (B,F,T) with STG.128 ----
    __syncthreads();               // all warps done with union before reuse
    {
        float* stg = &S.stage[wid][0];
        #pragma unroll
        for (int i = 0; i < CH; i++) stg[f_lo + i] = sp[i];
    }
    __syncthreads();
    {
        const int rb = blockIdx.x * WPB;
        const int t0 = rb & (TIME - 1);
        const int bb = rb >> 10;
        float4* ob = reinterpret_cast<float4*>(out + (size_t)bb * N_STFT * TIME + t0);
        #pragma unroll 1
        for (int f = tid; f < N_STFT; f += THREADS) {
            float4 v = make_float4(S.stage[0][f], S.stage[1][f],
                                   S.stage[2][f], S.stage[3][f]);
            ob[(size_t)f * (TIME/4)] = v;
        }
    }
}

// ---------------- launch ----------------
extern "C" void kernel_launch(void* const* d_in, const int* in_sizes, int n_in,
                              void* d_out, int out_size) {
    const float* mel = nullptr;   // 4*128*1024
    const float* spi = nullptr;   // 4*1024*1025
    const float* fb  = nullptr;   // 1025*128
    for (int i = 0; i < n_in; i++) {
        if      (in_sizes[i] == BATCH * N_MELS * TIME) mel = (const float*)d_in[i];
        else if (in_sizes[i] == ROWS * N_STFT)         spi = (const float*)d_in[i];
        else if (in_sizes[i] == N_STFT * N_MELS)       fb  = (const float*)d_in[i];
    }
    float* out = (float*)d_out;

    build_tables_k<<<(FPAD*32 + 255)/256, 256>>>(fb);   // warp per frequency
    imel_k<<<ROWS/WPB, THREADS>>>(mel, spi, out);
}

// round 16
// speedup vs baseline: 1.1838x; 1.0839x over previous
#include <cuda_runtime.h>
#include <cstdint>

#define N_STFT   1025
#define N_MELS   128
#define BATCH    4
#define TIME     1024
#define ROWS     (BATCH*TIME)
#define MAX_ITER 20
#define LR       0.3f
#define MOM      0.9f
#define INVC     (2.0f/4096.0f)
#define CH       33            // bins per lane (32*33 = 1056 >= 1025)
#define WPB      4             // warps per CTA
#define RPB      8             // rows per CTA (2 per warp, packed f32x2)
#define THREADS  128
#define FPAD     (32*CH)       // 1056
#define NENT     132           // entries k = virtual mel + 1
#define EPITCH   40u           // entry pitch: 5 x 8B pairs, gcd(5,16)=1 -> conflict-free

typedef unsigned long long u64;

// ---------------- device globals ----------------
__device__ float         g_aw[FPAD];
__device__ unsigned char g_me[FPAD];
__device__ float2        g_w2[FPAD];   // (w0 sign-encoded, 1-w0)

// ---------------- table build: one warp per frequency ----------------
__global__ void build_tables_k(const float* __restrict__ fb) {
    int gw   = (blockIdx.x * blockDim.x + threadIdx.x) >> 5;
    int lane = threadIdx.x & 31;
    if (gw >= FPAD) return;
    if (gw >= N_STFT) {
        if (!lane) { g_aw[gw] = 1.0f; g_me[gw] = 129; }
        return;
    }
    const float* r = fb + (size_t)gw * N_MELS;
    int m4 = lane * 4;
    unsigned loc = 128u;
    #pragma unroll
    for (int k = 3; k >= 0; k--) if (r[m4 + k] != 0.f) loc = (unsigned)(m4 + k);
    #pragma unroll
    for (int o = 16; o; o >>= 1) {
        unsigned v = __shfl_xor_sync(0xffffffffu, loc, o);
        loc = v < loc ? v : loc;
    }
    if (!lane) {
        float aw; int me;
        if (loc >= 128u) {                    // all-zero row: f=0 or f=1024
            aw = 1.0f; me = (gw == 0) ? 0 : 129;
        } else {
            int m0 = (int)loc;
            float w0raw = r[m0];
            float w1raw = (m0 < N_MELS - 1) ? r[m0 + 1] : 0.f;
            if (m0 == 0 && w1raw == 0.f && w0raw < 1.0f) {
                me = 0;                        // ascending-only: virtual mel -1
                aw = fmaxf(1.0f - w0raw, 1e-6f);
            } else {
                me = m0 + 1; aw = w0raw;       // w1 = 1 - aw (overlap identity)
            }
        }
        g_aw[gw] = aw; g_me[gw] = (unsigned char)me;
    }
}

// second pass: sign-encode "mel changed vs f-1" into w0; also store 1-w0
__global__ void sign_k() {
    int f = blockIdx.x * blockDim.x + threadIdx.x;
    if (f >= FPAD) return;
    float aw = g_aw[f];
    int   me = (int)g_me[f];
    int   pm = (f > 0) ? (int)g_me[f - 1] : me;
    float w0s = (me != pm) ? -aw : aw;
    g_w2[f] = make_float2(w0s, 1.0f - aw);
}

// ---------------- asm helpers ----------------
__device__ __forceinline__ unsigned smaddr(const void* p) {
    return (unsigned)__cvta_generic_to_shared(p);
}
__device__ __forceinline__ u64 lds64(unsigned a) {
    u64 v; asm volatile("ld.shared.b64 %0, [%1];" : "=l"(v) : "r"(a)); return v;
}
__device__ __forceinline__ void sts64(unsigned a, u64 v) {
    asm volatile("st.shared.b64 [%0], %1;" :: "r"(a), "l"(v) : "memory");
}
#define PK2(d, x)      asm("mov.b64 %0, {%1, %1};" : "=l"(d) : "f"(x))
#define PKP(d, lo, hi) asm("mov.b64 %0, {%1, %2};" : "=l"(d) : "f"(lo), "f"(hi))
#define UPK(lo, hi, x) asm("mov.b64 {%0, %1}, %2;" : "=f"(lo), "=f"(hi) : "l"(x))
#define FMA2(d, a, b, c) asm("fma.rn.f32x2 %0, %1, %2, %3;" : "=l"(d) : "l"(a), "l"(b), "l"(c))
#define MUL2(d, a, b)    asm("mul.rn.f32x2 %0, %1, %2;"     : "=l"(d) : "l"(a), "l"(b))
#define ADD2(d, a, b)    asm("add.rn.f32x2 %0, %1, %2;"     : "=l"(d) : "l"(a), "l"(b))

// Entry (40 B): {e2 pair, acc0 pair, acc1 pair, acc2 pair, negmel pair}.
// Single control stream steers BOTH rows (packed in .b64). On mel change
// (sign(w0)<0): flush a0 pair -> acc0, shift a0<-a1, a1<-0, d0<-d1, d1<-pn,
// reload pn from two entries ahead of the new cursor (latency-hidden).
#define CTRL2(wsig) asm volatile(                        \
    "{\n\t.reg .pred p;\n\t"                             \
    "setp.lt.f32 p, %6, 0f00000000;\n\t"                 \
    "@p st.shared.b64 [%0+8], %1;\n\t"                   \
    "selp.b64 %1, %2, %1, p;\n\t"                        \
    "selp.b64 %2, 0, %2, p;\n\t"                         \
    "selp.b64 %3, %4, %3, p;\n\t"                        \
    "@p add.u32 %0, %0, 40;\n\t"                         \
    "selp.b64 %4, %5, %4, p;\n\t"                        \
    "@p ld.shared.b64 %5, [%0+80];\n\t}"                 \
    : "+r"(addr), "+l"(a0), "+l"(a1), "+l"(d0),          \
      "+l"(d1), "+l"(pn)                                 \
    : "f"(wsig) : "memory")
// forward-only variant (prologue)
#define CTRLF2(wsig) asm volatile(                       \
    "{\n\t.reg .pred p;\n\t"                             \
    "setp.lt.f32 p, %3, 0f00000000;\n\t"                 \
    "@p st.shared.b64 [%0+8], %1;\n\t"                   \
    "selp.b64 %1, %2, %1, p;\n\t"                        \
    "selp.b64 %2, 0, %2, p;\n\t"                         \
    "@p add.u32 %0, %0, 40;\n\t}"                        \
    : "+r"(addr), "+l"(a0), "+l"(a1)                     \
    : "f"(wsig) : "memory")

// ---------------- shared: iteration phase / epilogue stage union ----------------
struct __align__(16) SmemIter {
    float  ent[WPB][NENT][10];   // 40 B per entry, zero-initialized once
    float2 w2s[FPAD];            // (w0 signed, 1-w0), CTA-shared
};
union __align__(16) SmemU {
    SmemIter it;
    float    stage[RPB][FPAD];
};

// ---------------- main: warp = two (b,t) rows; 20 fused iterations ----------------
__global__ void __launch_bounds__(THREADS, 3)
imel_k(const float* __restrict__ mel, const float* __restrict__ spi,
       float* __restrict__ out)
{
    __shared__ SmemU S;
    const int tid  = threadIdx.x;
    const int wid  = tid >> 5;
    const int lane = tid & 31;
    const int r0   = blockIdx.x * RPB + wid * 2;   // this warp: rows r0, r0+1
    const int b    = r0 >> 10;
    const int t    = r0 & (TIME - 1);              // even; rows share b

    // one-time zero of all entries (write pattern static across iterations)
    {
        float4  z  = make_float4(0.f, 0.f, 0.f, 0.f);
        float4* pz = reinterpret_cast<float4*>(&S.it.ent[0][0][0]);
        #pragma unroll 1
        for (int k = tid; k < WPB*NENT*10/4; k += THREADS) pz[k] = z;
    }
    // cooperative load of weight table
    #pragma unroll 1
    for (int k = tid; k < FPAD; k += THREADS) S.it.w2s[k] = g_w2[k];

    const int f_lo = lane * CH;

    // packed register state (lo = row r0, hi = row r0+1)
    u64 sp2[CH], bu2[CH];
    int me0 = (int)g_me[f_lo];
    {
        const float* s0 = spi + (size_t)r0 * N_STFT;
        #pragma unroll
        for (int i = 0; i < CH; i++) {
            int f  = f_lo + i;
            int fc = f > N_STFT-1 ? N_STFT-1 : f;
            PKP(sp2[i], s0[fc], s0[N_STFT + fc]);
            bu2[i] = 0ull;
        }
    }
    u64 MOM2, NLR2, INVC2;
    PK2(MOM2, MOM); PK2(NLR2, -LR); PK2(INVC2, INVC);

    const unsigned entb = smaddr(&S.it.ent[wid][0][0]);
    const unsigned ad0  = entb + (unsigned)me0 * EPITCH;

    __syncthreads();   // zeros + w2s visible

    // per-warp negmel pairs into entry field +32 (after zeroing)
    #pragma unroll
    for (int j = 0; j < 4; j++) {
        int m = lane + 32*j;
        float2 mv = *reinterpret_cast<const float2*>(
            mel + (size_t)b * (N_MELS*TIME) + (size_t)m * TIME + t);
        u64 nm; PKP(nm, -INVC * mv.x, -INVC * mv.y);
        sts64(entb + (unsigned)(m + 1) * EPITCH + 32u, nm);
    }
    __syncwarp();

    // ---- prologue forward: scatter proj of iteration 0 ----
    {
        unsigned addr = ad0;
        u64 a0 = 0ull, a1 = 0ull;
        #pragma unroll
        for (int i = 0; i < CH; i++) {
            float2 w = S.it.w2s[f_lo + i];
            if (i > 0) CTRLF2(w.x);
            float aw = fabsf(w.x);
            u64 aw2, om2; PK2(aw2, aw); PK2(om2, w.y);
            FMA2(a0, sp2[i], aw2, a0);
            FMA2(a1, sp2[i], om2, a1);
        }
        sts64(addr + 16u, a0);   // acc1 of end entry
        sts64(addr + 64u, a1);   // acc2 of end entry + 1 (40 + 24)
    }
    __syncwarp();

    #pragma unroll 1
    for (int it = 0; it < MAX_ITER; it++) {
        // ---- combine: e2[m+1] = INVC*(acc0+acc1+acc2) - INVC*mel ----
        #pragma unroll
        for (int j = 0; j < 4; j++) {
            int m = lane + 32*j;
            unsigned ea = entb + (unsigned)(m + 1) * EPITCH;
            u64 x0 = lds64(ea + 8u);
            u64 x1 = lds64(ea + 16u);
            u64 x2 = lds64(ea + 24u);
            u64 nm = lds64(ea + 32u);
            u64 s, e;
            ADD2(s, x0, x1); ADD2(s, s, x2);
            FMA2(e, s, INVC2, nm);
            sts64(ea, e);
        }
        __syncwarp();

        // ---- fused backward(it) + forward(it+1), packed pair per op ----
        unsigned addr = ad0;
        u64 d0 = lds64(ad0);
        u64 d1 = lds64(ad0 + 40u);
        u64 pn = lds64(ad0 + 80u);
        u64 a0 = 0ull, a1 = 0ull;
        #pragma unroll
        for (int i = 0; i < CH; i++) {
            float2 w = S.it.w2s[f_lo + i];
            if (i > 0) CTRL2(w.x);
            float aw = fabsf(w.x);
            u64 aw2, om2; PK2(aw2, aw); PK2(om2, w.y);
            u64 tmp, g;
            MUL2(tmp, om2, d1);
            FMA2(g, aw2, d0, tmp);            // e[vm]*aw + e[vm+1]*(1-aw)
            FMA2(bu2[i], MOM2, bu2[i], g);
            FMA2(sp2[i], NLR2, bu2[i], sp2[i]);
            float lo, hi; UPK(lo, hi, sp2[i]);
            lo = fmaxf(lo, 0.f); hi = fmaxf(hi, 0.f);
            PKP(sp2[i], lo, hi);
            FMA2(a0, sp2[i], aw2, a0);        // forward for next iteration
            FMA2(a1, sp2[i], om2, a1);
        }
        sts64(addr + 16u, a0);
        sts64(addr + 64u, a1);
        __syncwarp();
    }

    // ---- epilogue: stage rows in shared, write (B,F,T) with STG.128 ----
    __syncthreads();               // all warps done with union before reuse
    {
        float* s0 = &S.stage[wid*2][0];
        float* s1 = &S.stage[wid*2 + 1][0];
        #pragma unroll
        for (int i = 0; i < CH; i++) {
            float lo, hi; UPK(lo, hi, sp2[i]);
            s0[f_lo + i] = lo;
            s1[f_lo + i] = hi;
        }
    }
    __syncthreads();
    {
        const int rb = blockIdx.x * RPB;
        const int t0 = rb & (TIME - 1);
        const int bb = rb >> 10;
        float* ob = out + (size_t)bb * N_STFT * TIME + t0;
        #pragma unroll 1
        for (int f = tid; f < N_STFT; f += THREADS) {
            float4 v0 = make_float4(S.stage[0][f], S.stage[1][f],
                                    S.stage[2][f], S.stage[3][f]);
            float4 v1 = make_float4(S.stage[4][f], S.stage[5][f],
                                    S.stage[6][f], S.stage[7][f]);
            float4* p = reinterpret_cast<float4*>(ob + (size_t)f * TIME);
            p[0] = v0;
            p[1] = v1;
        }
    }
}

// ---------------- launch ----------------
extern "C" void kernel_launch(void* const* d_in, const int* in_sizes, int n_in,
                              void* d_out, int out_size) {
    const float* mel = nullptr;   // 4*128*1024
    const float* spi = nullptr;   // 4*1024*1025
    const float* fb  = nullptr;   // 1025*128
    for (int i = 0; i < n_in; i++) {
        if      (in_sizes[i] == BATCH * N_MELS * TIME) mel = (const float*)d_in[i];
        else if (in_sizes[i] == ROWS * N_STFT)         spi = (const float*)d_in[i];
        else if (in_sizes[i] == N_STFT * N_MELS)       fb  = (const float*)d_in[i];
    }
    float* out = (float*)d_out;

    build_tables_k<<<(FPAD*32 + 255)/256, 256>>>(fb);   // warp per frequency
    sign_k<<<(FPAD + 255)/256, 256>>>();
    imel_k<<<ROWS/RPB, THREADS>>>(mel, spi, out);
}